// round 3
// baseline (speedup 1.0000x reference)
#include <cuda_runtime.h>

#define N_NODES 50000
#define N_EDGES 800000
#define IN_F 32
#define H 64
#define GQ 512
#define OUTF 2
#define NLAYER 3
#define BN_EPS 1e-5f
#define PN_EPS 1e-5f

// ---------------- scratch (static device globals; no allocation) ----------------
__device__ float g_h[N_NODES * H];
__device__ float g_agg[N_NODES * H];
__device__ int   g_deg[N_NODES];
__device__ int   g_rowstart[N_NODES + 1];
__device__ int   g_cursor[N_NODES];
__device__ int   g_csr_src[N_EDGES];
__device__ float4 g_csr_attr[N_EDGES];
__device__ int   g_gcnt[GQ];
__device__ int   g_gstart[GQ + 1];

// ---------------- zero counters ----------------
__global__ void k_zero() {
    int i = blockIdx.x * blockDim.x + threadIdx.x;
    if (i < N_NODES) g_deg[i] = 0;
    if (i < GQ) g_gcnt[i] = 0;
}

// ---------------- histogram: in-degree per dst node + nodes per graph ----------------
__global__ void k_hist(const int* __restrict__ ei, const int* __restrict__ batch) {
    int i = blockIdx.x * blockDim.x + threadIdx.x;
    if (i < N_EDGES) atomicAdd(&g_deg[ei[N_EDGES + i]], 1);
    if (i < N_NODES) atomicAdd(&g_gcnt[batch[i]], 1);
}

// ---------------- exclusive scan of g_deg -> g_rowstart / g_cursor (single block) ----------------
__global__ void k_scan_deg() {
    __shared__ int ssum[1024];
    const int t = threadIdx.x;
    const int C = (N_NODES + 1023) / 1024;  // 49
    int start = t * C;
    int end = min(start + C, N_NODES);
    int local = 0;
    for (int i = start; i < end; i++) local += g_deg[i];
    ssum[t] = local;
    __syncthreads();
    // Hillis-Steele inclusive scan
    for (int off = 1; off < 1024; off <<= 1) {
        int v = 0;
        if (t >= off) v = ssum[t - off];
        __syncthreads();
        if (t >= off) ssum[t] += v;
        __syncthreads();
    }
    int prefix = (t == 0) ? 0 : ssum[t - 1];
    for (int i = start; i < end; i++) {
        g_rowstart[i] = prefix;
        g_cursor[i] = prefix;
        prefix += g_deg[i];
    }
    if (t == 1023) g_rowstart[N_NODES] = ssum[1023];
}

// ---------------- exclusive scan of g_gcnt -> g_gstart (single block, 512 threads) ----------------
__global__ void k_scan_g() {
    __shared__ int s[GQ];
    const int t = threadIdx.x;
    s[t] = g_gcnt[t];
    __syncthreads();
    for (int off = 1; off < GQ; off <<= 1) {
        int v = 0;
        if (t >= off) v = s[t - off];
        __syncthreads();
        if (t >= off) s[t] += v;
        __syncthreads();
    }
    g_gstart[t + 1] = s[t];
    if (t == 0) g_gstart[0] = 0;
}

// ---------------- fill CSR: src index + edge_attr packed, grouped by dst ----------------
__global__ void k_fill(const int* __restrict__ ei, const float* __restrict__ ea) {
    int e = blockIdx.x * blockDim.x + threadIdx.x;
    if (e >= N_EDGES) return;
    int dst = ei[N_EDGES + e];
    int pos = atomicAdd(&g_cursor[dst], 1);
    g_csr_src[pos] = ei[e];
    g_csr_attr[pos] = *(const float4*)(ea + e * 4);
}

// ---------------- h = x @ Win + b ----------------
__global__ void __launch_bounds__(128) k_lin_in(const float* __restrict__ x,
                                                const float* __restrict__ W,
                                                const float* __restrict__ b) {
    __shared__ float sW[IN_F * H];
    __shared__ float sb[H];
    for (int i = threadIdx.x; i < IN_F * H; i += 128) sW[i] = W[i];
    if (threadIdx.x < H) sb[threadIdx.x] = b[threadIdx.x];
    __syncthreads();
    int n = blockIdx.x * 128 + threadIdx.x;
    if (n >= N_NODES) return;
    float xr[IN_F];
    const float4* xp = (const float4*)(x + (size_t)n * IN_F);
#pragma unroll
    for (int k = 0; k < IN_F / 4; k++) {
        float4 v = xp[k];
        xr[4 * k + 0] = v.x; xr[4 * k + 1] = v.y; xr[4 * k + 2] = v.z; xr[4 * k + 3] = v.w;
    }
#pragma unroll
    for (int f = 0; f < H; f += 4) {
        float4 acc = make_float4(sb[f], sb[f + 1], sb[f + 2], sb[f + 3]);
#pragma unroll
        for (int k = 0; k < IN_F; k++) {
            float4 w = *(const float4*)&sW[k * H + f];
            acc.x = fmaf(xr[k], w.x, acc.x);
            acc.y = fmaf(xr[k], w.y, acc.y);
            acc.z = fmaf(xr[k], w.z, acc.z);
            acc.w = fmaf(xr[k], w.w, acc.w);
        }
        *(float4*)&g_h[(size_t)n * H + f] = acc;
    }
}

// ---------------- per-layer edge aggregation: agg[dst] = sum relu(h[src] + attr@eW + eb) ----------------
// one warp per destination node; each lane owns 2 features
__global__ void k_edge(const float* __restrict__ eW, const float* __restrict__ eb) {
    int warp = (blockIdx.x * blockDim.x + threadIdx.x) >> 5;
    int lane = threadIdx.x & 31;
    if (warp >= N_NODES) return;
    int f0 = lane * 2;
    float w00 = eW[f0],       w01 = eW[f0 + 1];
    float w10 = eW[64 + f0],  w11 = eW[64 + f0 + 1];
    float w20 = eW[128 + f0], w21 = eW[128 + f0 + 1];
    float w30 = eW[192 + f0], w31 = eW[192 + f0 + 1];
    float b0 = eb[f0], b1 = eb[f0 + 1];
    int js = g_rowstart[warp], je = g_rowstart[warp + 1];
    float a0 = 0.f, a1 = 0.f;
    for (int j = js; j < je; j++) {
        int src = g_csr_src[j];
        float4 at = g_csr_attr[j];
        float2 hs = *(const float2*)&g_h[(size_t)src * H + f0];
        float e0 = fmaf(at.w, w30, fmaf(at.z, w20, fmaf(at.y, w10, fmaf(at.x, w00, b0))));
        float e1 = fmaf(at.w, w31, fmaf(at.z, w21, fmaf(at.y, w11, fmaf(at.x, w01, b1))));
        a0 += fmaxf(hs.x + e0, 0.f);
        a1 += fmaxf(hs.y + e1, 0.f);
    }
    *(float2*)&g_agg[(size_t)warp * H + f0] = make_float2(a0, a1);
}

// ---------------- per-layer node update: z=(1+eps)h+agg; relu(bn(z@W1+b1)); @W2+b2; relu(bn) ----------------
__global__ void __launch_bounds__(128) k_node(
    const float* __restrict__ W1, const float* __restrict__ b1,
    const float* __restrict__ bn1g, const float* __restrict__ bn1b,
    const float* __restrict__ bn1rm, const float* __restrict__ bn1rv,
    const float* __restrict__ W2, const float* __restrict__ b2,
    const float* __restrict__ bn2g, const float* __restrict__ bn2b,
    const float* __restrict__ bn2rm, const float* __restrict__ bn2rv,
    const float* __restrict__ epsp) {
    __shared__ float sW1[H * H];
    __shared__ float sW2[H * H];
    __shared__ float sA1[H], sB1[H], sA2[H], sB2[H];
    for (int i = threadIdx.x; i < H * H; i += 128) { sW1[i] = W1[i]; sW2[i] = W2[i]; }
    if (threadIdx.x < H) {
        int f = threadIdx.x;
        float a1 = bn1g[f] * rsqrtf(bn1rv[f] + BN_EPS);
        sA1[f] = a1;
        sB1[f] = (b1[f] - bn1rm[f]) * a1 + bn1b[f];
        float a2 = bn2g[f] * rsqrtf(bn2rv[f] + BN_EPS);
        sA2[f] = a2;
        sB2[f] = (b2[f] - bn2rm[f]) * a2 + bn2b[f];
    }
    __syncthreads();
    int n = blockIdx.x * 128 + threadIdx.x;
    if (n >= N_NODES) return;
    float epsv = 1.0f + *epsp;
    float z[H];
#pragma unroll
    for (int k = 0; k < H; k += 4) {
        float4 hv = *(const float4*)&g_h[(size_t)n * H + k];
        float4 av = *(const float4*)&g_agg[(size_t)n * H + k];
        z[k + 0] = fmaf(epsv, hv.x, av.x);
        z[k + 1] = fmaf(epsv, hv.y, av.y);
        z[k + 2] = fmaf(epsv, hv.z, av.z);
        z[k + 3] = fmaf(epsv, hv.w, av.w);
    }
    float t[H];
#pragma unroll
    for (int f = 0; f < H; f += 4) {
        float4 acc = make_float4(0.f, 0.f, 0.f, 0.f);
#pragma unroll
        for (int k = 0; k < H; k++) {
            float4 w = *(const float4*)&sW1[k * H + f];
            acc.x = fmaf(z[k], w.x, acc.x);
            acc.y = fmaf(z[k], w.y, acc.y);
            acc.z = fmaf(z[k], w.z, acc.z);
            acc.w = fmaf(z[k], w.w, acc.w);
        }
        t[f + 0] = fmaxf(fmaf(acc.x, sA1[f + 0], sB1[f + 0]), 0.f);
        t[f + 1] = fmaxf(fmaf(acc.y, sA1[f + 1], sB1[f + 1]), 0.f);
        t[f + 2] = fmaxf(fmaf(acc.z, sA1[f + 2], sB1[f + 2]), 0.f);
        t[f + 3] = fmaxf(fmaf(acc.w, sA1[f + 3], sB1[f + 3]), 0.f);
    }
#pragma unroll
    for (int f = 0; f < H; f += 4) {
        float4 acc = make_float4(0.f, 0.f, 0.f, 0.f);
#pragma unroll
        for (int k = 0; k < H; k++) {
            float4 w = *(const float4*)&sW2[k * H + f];
            acc.x = fmaf(t[k], w.x, acc.x);
            acc.y = fmaf(t[k], w.y, acc.y);
            acc.z = fmaf(t[k], w.z, acc.z);
            acc.w = fmaf(t[k], w.w, acc.w);
        }
        float4 o;
        o.x = fmaxf(fmaf(acc.x, sA2[f + 0], sB2[f + 0]), 0.f);
        o.y = fmaxf(fmaf(acc.y, sA2[f + 1], sB2[f + 1]), 0.f);
        o.z = fmaxf(fmaf(acc.z, sA2[f + 2], sB2[f + 2]), 0.f);
        o.w = fmaxf(fmaf(acc.w, sA2[f + 3], sB2[f + 3]), 0.f);
        *(float4*)&g_h[(size_t)n * H + f] = o;
    }
}

// ---------------- PairNorm per graph segment (batch is sorted) ----------------
// block per graph, 64 threads = 1 feature per thread
__global__ void k_pairnorm() {
    __shared__ float red[H];
    __shared__ float s_mean[H];
    __shared__ float s_inv;
    int g = blockIdx.x, f = threadIdx.x;
    int ns = g_gstart[g], ne = g_gstart[g + 1];
    float cnt = fmaxf((float)(ne - ns), 1.f);
    float s = 0.f, ss = 0.f;
    for (int n = ns; n < ne; n++) {
        float v = g_h[(size_t)n * H + f];
        s += v;
        ss = fmaf(v, v, ss);
    }
    float mean = s / cnt;
    s_mean[f] = mean;
    red[f] = ss - cnt * mean * mean;  // per-feature centered sum of squares
    __syncthreads();
    for (int off = 32; off > 0; off >>= 1) {
        if (f < off) red[f] += red[f + off];
        __syncthreads();
    }
    if (f == 0) s_inv = 1.0f / sqrtf(PN_EPS + red[0] / cnt);  // PN_SCALE = 1
    __syncthreads();
    float inv = s_inv, m = s_mean[f];
    for (int n = ns; n < ne; n++) {
        g_h[(size_t)n * H + f] = (g_h[(size_t)n * H + f] - m) * inv;
    }
}

// ---------------- global_add_pool + classifier fused ----------------
__global__ void k_pool_cls(const float* __restrict__ clsW, const float* __restrict__ clsb,
                           float* __restrict__ out) {
    __shared__ float r0[H], r1[H];
    int g = blockIdx.x, f = threadIdx.x;
    int ns = g_gstart[g], ne = g_gstart[g + 1];
    float s = 0.f;
    for (int n = ns; n < ne; n++) s += g_h[(size_t)n * H + f];
    r0[f] = s * clsW[f * OUTF + 0];
    r1[f] = s * clsW[f * OUTF + 1];
    __syncthreads();
    for (int off = 32; off > 0; off >>= 1) {
        if (f < off) { r0[f] += r0[f + off]; r1[f] += r1[f + off]; }
        __syncthreads();
    }
    if (f == 0) {
        out[g * OUTF + 0] = r0[0] + clsb[0];
        out[g * OUTF + 1] = r1[0] + clsb[1];
    }
}

// ---------------- launcher ----------------
extern "C" void kernel_launch(void* const* d_in, const int* in_sizes, int n_in,
                              void* d_out, int out_size) {
    const float* x        = (const float*)d_in[0];
    const int*   ei       = (const int*)d_in[1];
    const float* ea       = (const float*)d_in[2];
    const int*   batch    = (const int*)d_in[3];
    const float* lin_in_W = (const float*)d_in[4];
    const float* lin_in_b = (const float*)d_in[5];
    const float* edge_W   = (const float*)d_in[6];
    const float* edge_b   = (const float*)d_in[7];
    const float* mlp_W1   = (const float*)d_in[8];
    const float* mlp_b1   = (const float*)d_in[9];
    const float* mlp_bn_g = (const float*)d_in[10];
    const float* mlp_bn_b = (const float*)d_in[11];
    const float* mlp_bn_rm= (const float*)d_in[12];
    const float* mlp_bn_rv= (const float*)d_in[13];
    const float* mlp_W2   = (const float*)d_in[14];
    const float* mlp_b2   = (const float*)d_in[15];
    const float* eps      = (const float*)d_in[16];
    const float* bn_g     = (const float*)d_in[17];
    const float* bn_b     = (const float*)d_in[18];
    const float* bn_rm    = (const float*)d_in[19];
    const float* bn_rv    = (const float*)d_in[20];
    const float* cls_W    = (const float*)d_in[21];
    const float* cls_b    = (const float*)d_in[22];
    float* out = (float*)d_out;

    k_zero<<<(N_NODES + 255) / 256, 256>>>();
    k_hist<<<(N_EDGES + 255) / 256, 256>>>(ei, batch);
    k_scan_deg<<<1, 1024>>>();
    k_scan_g<<<1, GQ>>>();
    k_fill<<<(N_EDGES + 255) / 256, 256>>>(ei, ea);
    k_lin_in<<<(N_NODES + 127) / 128, 128>>>(x, lin_in_W, lin_in_b);

    for (int i = 0; i < NLAYER; i++) {
        k_edge<<<(N_NODES * 32 + 255) / 256, 256>>>(edge_W + i * 4 * H, edge_b + i * H);
        k_node<<<(N_NODES + 127) / 128, 128>>>(
            mlp_W1 + i * H * H, mlp_b1 + i * H,
            mlp_bn_g + i * H, mlp_bn_b + i * H, mlp_bn_rm + i * H, mlp_bn_rv + i * H,
            mlp_W2 + i * H * H, mlp_b2 + i * H,
            bn_g + i * H, bn_b + i * H, bn_rm + i * H, bn_rv + i * H,
            eps + i);
        if (i < NLAYER - 1) k_pairnorm<<<GQ, H>>>();
    }
    k_pool_cls<<<GQ, H>>>(cls_W, cls_b, out);
}

// round 10
// speedup vs baseline: 1.1277x; 1.1277x over previous
#include <cuda_runtime.h>

#define N_NODES 50000
#define N_EDGES 800000
#define IN_F 32
#define H 64
#define GQ 512
#define OUTF 2
#define NLAYER 3
#define BN_EPS 1e-5f
#define PN_EPS 1e-5f

// ---------------- scratch (static device globals; no allocation) ----------------
__device__ float g_h[N_NODES * H];
__device__ float g_agg[N_NODES * H];
__device__ int   g_deg[N_NODES];
__device__ int   g_rowstart[N_NODES + 1];
__device__ int   g_cursor[N_NODES];
__device__ int   g_csr_src[N_EDGES];
__device__ float4 g_csr_attr[N_EDGES];
__device__ int   g_gcnt[GQ];
__device__ int   g_gstart[GQ + 1];

// ---------------- zero counters ----------------
__global__ void k_zero() {
    int i = blockIdx.x * blockDim.x + threadIdx.x;
    if (i < N_NODES) g_deg[i] = 0;
    if (i < GQ) g_gcnt[i] = 0;
}

// ---------------- histogram: in-degree per dst node + nodes per graph ----------------
__global__ void k_hist(const int* __restrict__ ei, const int* __restrict__ batch) {
    int i = blockIdx.x * blockDim.x + threadIdx.x;
    if (i < N_EDGES) atomicAdd(&g_deg[ei[N_EDGES + i]], 1);
    if (i < N_NODES) atomicAdd(&g_gcnt[batch[i]], 1);
}

// ---------------- both exclusive scans in one launch (block 0: deg, block 1: graphs) ----
__global__ void k_scans() {
    if (blockIdx.x == 0) {
        __shared__ int ssum[1024];
        const int t = threadIdx.x;
        const int C = (N_NODES + 1023) / 1024;  // 49
        int start = t * C;
        int end = min(start + C, N_NODES);
        int local = 0;
        for (int i = start; i < end; i++) local += g_deg[i];
        ssum[t] = local;
        __syncthreads();
        for (int off = 1; off < 1024; off <<= 1) {
            int v = 0;
            if (t >= off) v = ssum[t - off];
            __syncthreads();
            if (t >= off) ssum[t] += v;
            __syncthreads();
        }
        int prefix = (t == 0) ? 0 : ssum[t - 1];
        for (int i = start; i < end; i++) {
            g_rowstart[i] = prefix;
            g_cursor[i] = prefix;
            prefix += g_deg[i];
        }
        if (t == 1023) g_rowstart[N_NODES] = ssum[1023];
    } else {
        __shared__ int s[GQ];
        const int t = threadIdx.x;
        if (t < GQ) s[t] = g_gcnt[t];
        __syncthreads();
        for (int off = 1; off < GQ; off <<= 1) {
            int v = 0;
            if (t < GQ && t >= off) v = s[t - off];
            __syncthreads();
            if (t < GQ && t >= off) s[t] += v;
            __syncthreads();
        }
        if (t < GQ) g_gstart[t + 1] = s[t];
        if (t == 0) g_gstart[0] = 0;
    }
}

// ---------------- fill CSR: src index + edge_attr packed, grouped by dst ----------------
__global__ void k_fill(const int* __restrict__ ei, const float* __restrict__ ea) {
    int e = blockIdx.x * blockDim.x + threadIdx.x;
    if (e >= N_EDGES) return;
    int dst = ei[N_EDGES + e];
    int pos = atomicAdd(&g_cursor[dst], 1);
    g_csr_src[pos] = ei[e];
    g_csr_attr[pos] = *(const float4*)(ea + e * 4);
}

// ---------------- h = x @ Win + b ----------------
__global__ void __launch_bounds__(128) k_lin_in(const float* __restrict__ x,
                                                const float* __restrict__ W,
                                                const float* __restrict__ b) {
    __shared__ float sW[IN_F * H];
    __shared__ float sb[H];
    for (int i = threadIdx.x; i < IN_F * H; i += 128) sW[i] = W[i];
    if (threadIdx.x < H) sb[threadIdx.x] = b[threadIdx.x];
    __syncthreads();
    int n = blockIdx.x * 128 + threadIdx.x;
    if (n >= N_NODES) return;
    float xr[IN_F];
    const float4* xp = (const float4*)(x + (size_t)n * IN_F);
#pragma unroll
    for (int k = 0; k < IN_F / 4; k++) {
        float4 v = xp[k];
        xr[4 * k + 0] = v.x; xr[4 * k + 1] = v.y; xr[4 * k + 2] = v.z; xr[4 * k + 3] = v.w;
    }
#pragma unroll
    for (int f = 0; f < H; f += 4) {
        float4 acc = make_float4(sb[f], sb[f + 1], sb[f + 2], sb[f + 3]);
#pragma unroll
        for (int k = 0; k < IN_F; k++) {
            float4 w = *(const float4*)&sW[k * H + f];
            acc.x = fmaf(xr[k], w.x, acc.x);
            acc.y = fmaf(xr[k], w.y, acc.y);
            acc.z = fmaf(xr[k], w.z, acc.z);
            acc.w = fmaf(xr[k], w.w, acc.w);
        }
        *(float4*)&g_h[(size_t)n * H + f] = acc;
    }
}

// ---------------- per-layer edge aggregation (warp per dst, unroll-4 pipelined) ----------
__global__ void k_edge(const float* __restrict__ eW, const float* __restrict__ eb) {
    int warp = (blockIdx.x * blockDim.x + threadIdx.x) >> 5;
    int lane = threadIdx.x & 31;
    if (warp >= N_NODES) return;
    int f0 = lane * 2;
    float w00 = eW[f0],       w01 = eW[f0 + 1];
    float w10 = eW[64 + f0],  w11 = eW[64 + f0 + 1];
    float w20 = eW[128 + f0], w21 = eW[128 + f0 + 1];
    float w30 = eW[192 + f0], w31 = eW[192 + f0 + 1];
    float b0 = eb[f0], b1 = eb[f0 + 1];
    int js = g_rowstart[warp], je = g_rowstart[warp + 1];
    float a0 = 0.f, a1 = 0.f;
    int j = js;
    // unroll-4: batch independent src/attr loads, then 4 h-gathers in flight
    for (; j + 4 <= je; j += 4) {
        int s0 = __ldg(&g_csr_src[j + 0]);
        int s1 = __ldg(&g_csr_src[j + 1]);
        int s2 = __ldg(&g_csr_src[j + 2]);
        int s3 = __ldg(&g_csr_src[j + 3]);
        float4 t0 = __ldg(&g_csr_attr[j + 0]);
        float4 t1 = __ldg(&g_csr_attr[j + 1]);
        float4 t2 = __ldg(&g_csr_attr[j + 2]);
        float4 t3 = __ldg(&g_csr_attr[j + 3]);
        float2 h0 = *(const float2*)&g_h[(size_t)s0 * H + f0];
        float2 h1 = *(const float2*)&g_h[(size_t)s1 * H + f0];
        float2 h2 = *(const float2*)&g_h[(size_t)s2 * H + f0];
        float2 h3 = *(const float2*)&g_h[(size_t)s3 * H + f0];
        float e;
        e = fmaf(t0.w, w30, fmaf(t0.z, w20, fmaf(t0.y, w10, fmaf(t0.x, w00, b0))));
        a0 += fmaxf(h0.x + e, 0.f);
        e = fmaf(t0.w, w31, fmaf(t0.z, w21, fmaf(t0.y, w11, fmaf(t0.x, w01, b1))));
        a1 += fmaxf(h0.y + e, 0.f);
        e = fmaf(t1.w, w30, fmaf(t1.z, w20, fmaf(t1.y, w10, fmaf(t1.x, w00, b0))));
        a0 += fmaxf(h1.x + e, 0.f);
        e = fmaf(t1.w, w31, fmaf(t1.z, w21, fmaf(t1.y, w11, fmaf(t1.x, w01, b1))));
        a1 += fmaxf(h1.y + e, 0.f);
        e = fmaf(t2.w, w30, fmaf(t2.z, w20, fmaf(t2.y, w10, fmaf(t2.x, w00, b0))));
        a0 += fmaxf(h2.x + e, 0.f);
        e = fmaf(t2.w, w31, fmaf(t2.z, w21, fmaf(t2.y, w11, fmaf(t2.x, w01, b1))));
        a1 += fmaxf(h2.y + e, 0.f);
        e = fmaf(t3.w, w30, fmaf(t3.z, w20, fmaf(t3.y, w10, fmaf(t3.x, w00, b0))));
        a0 += fmaxf(h3.x + e, 0.f);
        e = fmaf(t3.w, w31, fmaf(t3.z, w21, fmaf(t3.y, w11, fmaf(t3.x, w01, b1))));
        a1 += fmaxf(h3.y + e, 0.f);
    }
    for (; j < je; j++) {
        int src = __ldg(&g_csr_src[j]);
        float4 at = __ldg(&g_csr_attr[j]);
        float2 hs = *(const float2*)&g_h[(size_t)src * H + f0];
        float e0 = fmaf(at.w, w30, fmaf(at.z, w20, fmaf(at.y, w10, fmaf(at.x, w00, b0))));
        float e1 = fmaf(at.w, w31, fmaf(at.z, w21, fmaf(at.y, w11, fmaf(at.x, w01, b1))));
        a0 += fmaxf(hs.x + e0, 0.f);
        a1 += fmaxf(hs.y + e1, 0.f);
    }
    *(float2*)&g_agg[(size_t)warp * H + f0] = make_float2(a0, a1);
}

// ---------------- per-layer node update: z=(1+eps)h+agg; relu(bn(z@W1+b1)); @W2+b2; relu(bn) ----------------
__global__ void __launch_bounds__(128) k_node(
    const float* __restrict__ W1, const float* __restrict__ b1,
    const float* __restrict__ bn1g, const float* __restrict__ bn1b,
    const float* __restrict__ bn1rm, const float* __restrict__ bn1rv,
    const float* __restrict__ W2, const float* __restrict__ b2,
    const float* __restrict__ bn2g, const float* __restrict__ bn2b,
    const float* __restrict__ bn2rm, const float* __restrict__ bn2rv,
    const float* __restrict__ epsp) {
    __shared__ float sW1[H * H];
    __shared__ float sW2[H * H];
    __shared__ float sA1[H], sB1[H], sA2[H], sB2[H];
    for (int i = threadIdx.x; i < H * H; i += 128) { sW1[i] = W1[i]; sW2[i] = W2[i]; }
    if (threadIdx.x < H) {
        int f = threadIdx.x;
        float a1 = bn1g[f] * rsqrtf(bn1rv[f] + BN_EPS);
        sA1[f] = a1;
        sB1[f] = (b1[f] - bn1rm[f]) * a1 + bn1b[f];
        float a2 = bn2g[f] * rsqrtf(bn2rv[f] + BN_EPS);
        sA2[f] = a2;
        sB2[f] = (b2[f] - bn2rm[f]) * a2 + bn2b[f];
    }
    __syncthreads();
    int n = blockIdx.x * 128 + threadIdx.x;
    if (n >= N_NODES) return;
    float epsv = 1.0f + *epsp;
    float z[H];
#pragma unroll
    for (int k = 0; k < H; k += 4) {
        float4 hv = *(const float4*)&g_h[(size_t)n * H + k];
        float4 av = *(const float4*)&g_agg[(size_t)n * H + k];
        z[k + 0] = fmaf(epsv, hv.x, av.x);
        z[k + 1] = fmaf(epsv, hv.y, av.y);
        z[k + 2] = fmaf(epsv, hv.z, av.z);
        z[k + 3] = fmaf(epsv, hv.w, av.w);
    }
    float t[H];
#pragma unroll
    for (int f = 0; f < H; f += 4) {
        float4 acc = make_float4(0.f, 0.f, 0.f, 0.f);
#pragma unroll
        for (int k = 0; k < H; k++) {
            float4 w = *(const float4*)&sW1[k * H + f];
            acc.x = fmaf(z[k], w.x, acc.x);
            acc.y = fmaf(z[k], w.y, acc.y);
            acc.z = fmaf(z[k], w.z, acc.z);
            acc.w = fmaf(z[k], w.w, acc.w);
        }
        t[f + 0] = fmaxf(fmaf(acc.x, sA1[f + 0], sB1[f + 0]), 0.f);
        t[f + 1] = fmaxf(fmaf(acc.y, sA1[f + 1], sB1[f + 1]), 0.f);
        t[f + 2] = fmaxf(fmaf(acc.z, sA1[f + 2], sB1[f + 2]), 0.f);
        t[f + 3] = fmaxf(fmaf(acc.w, sA1[f + 3], sB1[f + 3]), 0.f);
    }
#pragma unroll
    for (int f = 0; f < H; f += 4) {
        float4 acc = make_float4(0.f, 0.f, 0.f, 0.f);
#pragma unroll
        for (int k = 0; k < H; k++) {
            float4 w = *(const float4*)&sW2[k * H + f];
            acc.x = fmaf(t[k], w.x, acc.x);
            acc.y = fmaf(t[k], w.y, acc.y);
            acc.z = fmaf(t[k], w.z, acc.z);
            acc.w = fmaf(t[k], w.w, acc.w);
        }
        float4 o;
        o.x = fmaxf(fmaf(acc.x, sA2[f + 0], sB2[f + 0]), 0.f);
        o.y = fmaxf(fmaf(acc.y, sA2[f + 1], sB2[f + 1]), 0.f);
        o.z = fmaxf(fmaf(acc.z, sA2[f + 2], sB2[f + 2]), 0.f);
        o.w = fmaxf(fmaf(acc.w, sA2[f + 3], sB2[f + 3]), 0.f);
        *(float4*)&g_h[(size_t)n * H + f] = o;
    }
}

// ---------------- PairNorm per graph segment: 256 threads, 4 rows in flight ----------------
__global__ void __launch_bounds__(256) k_pairnorm() {
    __shared__ float sS[4][H];
    __shared__ float sSS[4][H];
    __shared__ float sMean[H];
    __shared__ float sRed[H];
    __shared__ float sInv;
    int g = blockIdx.x;
    int sub = threadIdx.x >> 6, f = threadIdx.x & 63;
    int ns = g_gstart[g], ne = g_gstart[g + 1];
    float cnt = fmaxf((float)(ne - ns), 1.f);
    float s = 0.f, ss = 0.f;
    for (int n = ns + sub; n < ne; n += 4) {
        float v = g_h[(size_t)n * H + f];
        s += v;
        ss = fmaf(v, v, ss);
    }
    sS[sub][f] = s;
    sSS[sub][f] = ss;
    __syncthreads();
    if (sub == 0) {
        float st = sS[0][f] + sS[1][f] + sS[2][f] + sS[3][f];
        float sst = sSS[0][f] + sSS[1][f] + sSS[2][f] + sSS[3][f];
        float mean = st / cnt;
        sMean[f] = mean;
        sRed[f] = sst - cnt * mean * mean;
    }
    __syncthreads();
    if (threadIdx.x < 32) {
        float v = sRed[threadIdx.x] + sRed[threadIdx.x + 32];
#pragma unroll
        for (int o = 16; o > 0; o >>= 1) v += __shfl_down_sync(0xffffffffu, v, o);
        if (threadIdx.x == 0) sInv = 1.0f / sqrtf(PN_EPS + v / cnt);
    }
    __syncthreads();
    float inv = sInv, m = sMean[f];
    for (int n = ns + sub; n < ne; n += 4) {
        size_t idx = (size_t)n * H + f;
        g_h[idx] = (g_h[idx] - m) * inv;
    }
}

// ---------------- global_add_pool + classifier fused: 256 threads ----------------
__global__ void __launch_bounds__(256) k_pool_cls(const float* __restrict__ clsW,
                                                  const float* __restrict__ clsb,
                                                  float* __restrict__ out) {
    __shared__ float sS[4][H];
    __shared__ float r0[H], r1[H];
    int g = blockIdx.x;
    int sub = threadIdx.x >> 6, f = threadIdx.x & 63;
    int ns = g_gstart[g], ne = g_gstart[g + 1];
    float s = 0.f;
    for (int n = ns + sub; n < ne; n += 4) s += g_h[(size_t)n * H + f];
    sS[sub][f] = s;
    __syncthreads();
    if (sub == 0) {
        float st = sS[0][f] + sS[1][f] + sS[2][f] + sS[3][f];
        r0[f] = st * clsW[f * OUTF + 0];
        r1[f] = st * clsW[f * OUTF + 1];
    }
    __syncthreads();
    if (threadIdx.x < 32) {
        float v0 = r0[threadIdx.x] + r0[threadIdx.x + 32];
        float v1 = r1[threadIdx.x] + r1[threadIdx.x + 32];
#pragma unroll
        for (int o = 16; o > 0; o >>= 1) {
            v0 += __shfl_down_sync(0xffffffffu, v0, o);
            v1 += __shfl_down_sync(0xffffffffu, v1, o);
        }
        if (threadIdx.x == 0) {
            out[g * OUTF + 0] = v0 + clsb[0];
            out[g * OUTF + 1] = v1 + clsb[1];
        }
    }
}

// ---------------- launcher ----------------
extern "C" void kernel_launch(void* const* d_in, const int* in_sizes, int n_in,
                              void* d_out, int out_size) {
    const float* x        = (const float*)d_in[0];
    const int*   ei       = (const int*)d_in[1];
    const float* ea       = (const float*)d_in[2];
    const int*   batch    = (const int*)d_in[3];
    const float* lin_in_W = (const float*)d_in[4];
    const float* lin_in_b = (const float*)d_in[5];
    const float* edge_W   = (const float*)d_in[6];
    const float* edge_b   = (const float*)d_in[7];
    const float* mlp_W1   = (const float*)d_in[8];
    const float* mlp_b1   = (const float*)d_in[9];
    const float* mlp_bn_g = (const float*)d_in[10];
    const float* mlp_bn_b = (const float*)d_in[11];
    const float* mlp_bn_rm= (const float*)d_in[12];
    const float* mlp_bn_rv= (const float*)d_in[13];
    const float* mlp_W2   = (const float*)d_in[14];
    const float* mlp_b2   = (const float*)d_in[15];
    const float* eps      = (const float*)d_in[16];
    const float* bn_g     = (const float*)d_in[17];
    const float* bn_b     = (const float*)d_in[18];
    const float* bn_rm    = (const float*)d_in[19];
    const float* bn_rv    = (const float*)d_in[20];
    const float* cls_W    = (const float*)d_in[21];
    const float* cls_b    = (const float*)d_in[22];
    float* out = (float*)d_out;

    k_zero<<<(N_NODES + 255) / 256, 256>>>();
    k_hist<<<(N_EDGES + 255) / 256, 256>>>(ei, batch);
    k_scans<<<2, 1024>>>();
    k_fill<<<(N_EDGES + 255) / 256, 256>>>(ei, ea);
    k_lin_in<<<(N_NODES + 127) / 128, 128>>>(x, lin_in_W, lin_in_b);

    for (int i = 0; i < NLAYER; i++) {
        k_edge<<<(N_NODES * 32 + 255) / 256, 256>>>(edge_W + i * 4 * H, edge_b + i * H);
        k_node<<<(N_NODES + 127) / 128, 128>>>(
            mlp_W1 + i * H * H, mlp_b1 + i * H,
            mlp_bn_g + i * H, mlp_bn_b + i * H, mlp_bn_rm + i * H, mlp_bn_rv + i * H,
            mlp_W2 + i * H * H, mlp_b2 + i * H,
            bn_g + i * H, bn_b + i * H, bn_rm + i * H, bn_rv + i * H,
            eps + i);
        if (i < NLAYER - 1) k_pairnorm<<<GQ, 256>>>();
    }
    k_pool_cls<<<GQ, 256>>>(cls_W, cls_b, out);
}

// round 11
// speedup vs baseline: 1.1367x; 1.0079x over previous
#include <cuda_runtime.h>

#define N_NODES 50000
#define N_EDGES 800000
#define IN_F 32
#define H 64
#define GQ 512
#define OUTF 2
#define NLAYER 3
#define BN_EPS 1e-5f
#define PN_EPS 1e-5f
#define LIN_BLOCKS 391  /* (N_NODES+127)/128 */

// ---------------- scratch (static device globals; no allocation) ----------------
__device__ float g_h[N_NODES * H];
__device__ float g_agg[N_NODES * H];
__device__ int   g_deg[N_NODES];
__device__ int   g_rowstart[N_NODES + 1];
__device__ int   g_cursor[N_NODES];
__device__ int   g_csr_src[N_EDGES];
__device__ float4 g_csr_attr[N_EDGES];
__device__ int   g_gcnt[GQ];
__device__ int   g_gstart[GQ + 1];

// packed f32x2 helpers
__device__ __forceinline__ unsigned long long splat_f32x2(float v) {
    unsigned long long r;
    unsigned int u = __float_as_uint(v);
    asm("mov.b64 %0, {%1, %1};" : "=l"(r) : "r"(u));
    return r;
}
__device__ __forceinline__ void fma_f32x2(unsigned long long& acc,
                                          unsigned long long a,
                                          unsigned long long b) {
    asm("fma.rn.f32x2 %0, %1, %2, %0;" : "+l"(acc) : "l"(a), "l"(b));
}
__device__ __forceinline__ void unpack_f32x2(unsigned long long p, float& lo, float& hi) {
    unsigned int u0, u1;
    asm("mov.b64 {%0, %1}, %2;" : "=r"(u0), "=r"(u1) : "l"(p));
    lo = __uint_as_float(u0);
    hi = __uint_as_float(u1);
}

// ---------------- fused: zero counters (blocks >= LIN_BLOCKS) + h = x@Win + b ----------
__global__ void __launch_bounds__(128) k_zero_lin(const float* __restrict__ x,
                                                  const float* __restrict__ W,
                                                  const float* __restrict__ b) {
    if (blockIdx.x >= LIN_BLOCKS) {
        int i = (blockIdx.x - LIN_BLOCKS) * 128 + threadIdx.x;
        if (i < N_NODES) g_deg[i] = 0;
        if (i < GQ) g_gcnt[i] = 0;
        return;
    }
    __shared__ float sW[IN_F * H];
    __shared__ float sb[H];
    for (int i = threadIdx.x; i < IN_F * H; i += 128) sW[i] = W[i];
    if (threadIdx.x < H) sb[threadIdx.x] = b[threadIdx.x];
    __syncthreads();
    int n = blockIdx.x * 128 + threadIdx.x;
    if (n >= N_NODES) return;
    float xr[IN_F];
    const float4* xp = (const float4*)(x + (size_t)n * IN_F);
#pragma unroll
    for (int k = 0; k < IN_F / 4; k++) {
        float4 v = xp[k];
        xr[4 * k + 0] = v.x; xr[4 * k + 1] = v.y; xr[4 * k + 2] = v.z; xr[4 * k + 3] = v.w;
    }
#pragma unroll
    for (int f = 0; f < H; f += 4) {
        float4 acc = make_float4(sb[f], sb[f + 1], sb[f + 2], sb[f + 3]);
#pragma unroll
        for (int k = 0; k < IN_F; k++) {
            float4 w = *(const float4*)&sW[k * H + f];
            acc.x = fmaf(xr[k], w.x, acc.x);
            acc.y = fmaf(xr[k], w.y, acc.y);
            acc.z = fmaf(xr[k], w.z, acc.z);
            acc.w = fmaf(xr[k], w.w, acc.w);
        }
        *(float4*)&g_h[(size_t)n * H + f] = acc;
    }
}

// ---------------- histogram: in-degree per dst node + nodes per graph ----------------
__global__ void k_hist(const int* __restrict__ ei, const int* __restrict__ batch) {
    int i = blockIdx.x * blockDim.x + threadIdx.x;
    if (i < N_EDGES) atomicAdd(&g_deg[ei[N_EDGES + i]], 1);
    if (i < N_NODES) atomicAdd(&g_gcnt[batch[i]], 1);
}

// ---------------- both exclusive scans in one launch (block 0: deg, block 1: graphs) ----
__global__ void k_scans() {
    if (blockIdx.x == 0) {
        __shared__ int ssum[1024];
        const int t = threadIdx.x;
        const int C = (N_NODES + 1023) / 1024;  // 49
        int start = t * C;
        int end = min(start + C, N_NODES);
        int local = 0;
        for (int i = start; i < end; i++) local += g_deg[i];
        ssum[t] = local;
        __syncthreads();
        for (int off = 1; off < 1024; off <<= 1) {
            int v = 0;
            if (t >= off) v = ssum[t - off];
            __syncthreads();
            if (t >= off) ssum[t] += v;
            __syncthreads();
        }
        int prefix = (t == 0) ? 0 : ssum[t - 1];
        for (int i = start; i < end; i++) {
            g_rowstart[i] = prefix;
            g_cursor[i] = prefix;
            prefix += g_deg[i];
        }
        if (t == 1023) g_rowstart[N_NODES] = ssum[1023];
    } else {
        __shared__ int s[GQ];
        const int t = threadIdx.x;
        if (t < GQ) s[t] = g_gcnt[t];
        __syncthreads();
        for (int off = 1; off < GQ; off <<= 1) {
            int v = 0;
            if (t < GQ && t >= off) v = s[t - off];
            __syncthreads();
            if (t < GQ && t >= off) s[t] += v;
            __syncthreads();
        }
        if (t < GQ) g_gstart[t + 1] = s[t];
        if (t == 0) g_gstart[0] = 0;
    }
}

// ---------------- fill CSR: 2 edges per thread, vectorized loads ----------------
__global__ void k_fill(const int* __restrict__ ei, const float* __restrict__ ea) {
    int i = blockIdx.x * blockDim.x + threadIdx.x;
    int e0 = i * 2;
    if (e0 >= N_EDGES) return;
    int2 srcs = *(const int2*)(ei + e0);               // e0 even -> 8B aligned
    int2 dsts = *(const int2*)(ei + N_EDGES + e0);     // N_EDGES even
    float4 a0 = __ldg((const float4*)ea + e0);
    float4 a1 = __ldg((const float4*)ea + e0 + 1);
    int p0 = atomicAdd(&g_cursor[dsts.x], 1);
    g_csr_src[p0] = srcs.x;
    g_csr_attr[p0] = a0;
    int p1 = atomicAdd(&g_cursor[dsts.y], 1);
    g_csr_src[p1] = srcs.y;
    g_csr_attr[p1] = a1;
}

// ---------------- per-layer edge aggregation (warp per dst, unroll-4 pipelined) ----------
__global__ void k_edge(const float* __restrict__ eW, const float* __restrict__ eb) {
    int warp = (blockIdx.x * blockDim.x + threadIdx.x) >> 5;
    int lane = threadIdx.x & 31;
    if (warp >= N_NODES) return;
    int f0 = lane * 2;
    float w00 = eW[f0],       w01 = eW[f0 + 1];
    float w10 = eW[64 + f0],  w11 = eW[64 + f0 + 1];
    float w20 = eW[128 + f0], w21 = eW[128 + f0 + 1];
    float w30 = eW[192 + f0], w31 = eW[192 + f0 + 1];
    float b0 = eb[f0], b1 = eb[f0 + 1];
    int js = g_rowstart[warp], je = g_rowstart[warp + 1];
    float a0 = 0.f, a1 = 0.f;
    int j = js;
    for (; j + 4 <= je; j += 4) {
        int s0 = __ldg(&g_csr_src[j + 0]);
        int s1 = __ldg(&g_csr_src[j + 1]);
        int s2 = __ldg(&g_csr_src[j + 2]);
        int s3 = __ldg(&g_csr_src[j + 3]);
        float4 t0 = __ldg(&g_csr_attr[j + 0]);
        float4 t1 = __ldg(&g_csr_attr[j + 1]);
        float4 t2 = __ldg(&g_csr_attr[j + 2]);
        float4 t3 = __ldg(&g_csr_attr[j + 3]);
        float2 h0 = *(const float2*)&g_h[(size_t)s0 * H + f0];
        float2 h1 = *(const float2*)&g_h[(size_t)s1 * H + f0];
        float2 h2 = *(const float2*)&g_h[(size_t)s2 * H + f0];
        float2 h3 = *(const float2*)&g_h[(size_t)s3 * H + f0];
        float e;
        e = fmaf(t0.w, w30, fmaf(t0.z, w20, fmaf(t0.y, w10, fmaf(t0.x, w00, b0))));
        a0 += fmaxf(h0.x + e, 0.f);
        e = fmaf(t0.w, w31, fmaf(t0.z, w21, fmaf(t0.y, w11, fmaf(t0.x, w01, b1))));
        a1 += fmaxf(h0.y + e, 0.f);
        e = fmaf(t1.w, w30, fmaf(t1.z, w20, fmaf(t1.y, w10, fmaf(t1.x, w00, b0))));
        a0 += fmaxf(h1.x + e, 0.f);
        e = fmaf(t1.w, w31, fmaf(t1.z, w21, fmaf(t1.y, w11, fmaf(t1.x, w01, b1))));
        a1 += fmaxf(h1.y + e, 0.f);
        e = fmaf(t2.w, w30, fmaf(t2.z, w20, fmaf(t2.y, w10, fmaf(t2.x, w00, b0))));
        a0 += fmaxf(h2.x + e, 0.f);
        e = fmaf(t2.w, w31, fmaf(t2.z, w21, fmaf(t2.y, w11, fmaf(t2.x, w01, b1))));
        a1 += fmaxf(h2.y + e, 0.f);
        e = fmaf(t3.w, w30, fmaf(t3.z, w20, fmaf(t3.y, w10, fmaf(t3.x, w00, b0))));
        a0 += fmaxf(h3.x + e, 0.f);
        e = fmaf(t3.w, w31, fmaf(t3.z, w21, fmaf(t3.y, w11, fmaf(t3.x, w01, b1))));
        a1 += fmaxf(h3.y + e, 0.f);
    }
    for (; j < je; j++) {
        int src = __ldg(&g_csr_src[j]);
        float4 at = __ldg(&g_csr_attr[j]);
        float2 hs = *(const float2*)&g_h[(size_t)src * H + f0];
        float e0 = fmaf(at.w, w30, fmaf(at.z, w20, fmaf(at.y, w10, fmaf(at.x, w00, b0))));
        float e1 = fmaf(at.w, w31, fmaf(at.z, w21, fmaf(at.y, w11, fmaf(at.x, w01, b1))));
        a0 += fmaxf(hs.x + e0, 0.f);
        a1 += fmaxf(hs.y + e1, 0.f);
    }
    *(float2*)&g_agg[(size_t)warp * H + f0] = make_float2(a0, a1);
}

// ---------------- per-layer node update with packed f32x2 FMA ----------------
__global__ void __launch_bounds__(128) k_node(
    const float* __restrict__ W1, const float* __restrict__ b1,
    const float* __restrict__ bn1g, const float* __restrict__ bn1b,
    const float* __restrict__ bn1rm, const float* __restrict__ bn1rv,
    const float* __restrict__ W2, const float* __restrict__ b2,
    const float* __restrict__ bn2g, const float* __restrict__ bn2b,
    const float* __restrict__ bn2rm, const float* __restrict__ bn2rv,
    const float* __restrict__ epsp) {
    __shared__ __align__(16) float sW1[H * H];
    __shared__ __align__(16) float sW2[H * H];
    __shared__ float sA1[H], sB1[H], sA2[H], sB2[H];
    for (int i = threadIdx.x; i < H * H; i += 128) { sW1[i] = W1[i]; sW2[i] = W2[i]; }
    if (threadIdx.x < H) {
        int f = threadIdx.x;
        float a1 = bn1g[f] * rsqrtf(bn1rv[f] + BN_EPS);
        sA1[f] = a1;
        sB1[f] = (b1[f] - bn1rm[f]) * a1 + bn1b[f];
        float a2 = bn2g[f] * rsqrtf(bn2rv[f] + BN_EPS);
        sA2[f] = a2;
        sB2[f] = (b2[f] - bn2rm[f]) * a2 + bn2b[f];
    }
    __syncthreads();
    int n = blockIdx.x * 128 + threadIdx.x;
    if (n >= N_NODES) return;
    float epsv = 1.0f + *epsp;
    float z[H];
#pragma unroll
    for (int k = 0; k < H; k += 4) {
        float4 hv = *(const float4*)&g_h[(size_t)n * H + k];
        float4 av = *(const float4*)&g_agg[(size_t)n * H + k];
        z[k + 0] = fmaf(epsv, hv.x, av.x);
        z[k + 1] = fmaf(epsv, hv.y, av.y);
        z[k + 2] = fmaf(epsv, hv.z, av.z);
        z[k + 3] = fmaf(epsv, hv.w, av.w);
    }
    float t[H];
#pragma unroll
    for (int f = 0; f < H; f += 4) {
        unsigned long long acc01 = 0ull, acc23 = 0ull;  // packed (0,0)
#pragma unroll
        for (int k = 0; k < H; k++) {
            const ulonglong2 w = *(const ulonglong2*)&sW1[k * H + f];
            unsigned long long zz = splat_f32x2(z[k]);
            fma_f32x2(acc01, zz, w.x);
            fma_f32x2(acc23, zz, w.y);
        }
        float a0, a1, a2, a3;
        unpack_f32x2(acc01, a0, a1);
        unpack_f32x2(acc23, a2, a3);
        t[f + 0] = fmaxf(fmaf(a0, sA1[f + 0], sB1[f + 0]), 0.f);
        t[f + 1] = fmaxf(fmaf(a1, sA1[f + 1], sB1[f + 1]), 0.f);
        t[f + 2] = fmaxf(fmaf(a2, sA1[f + 2], sB1[f + 2]), 0.f);
        t[f + 3] = fmaxf(fmaf(a3, sA1[f + 3], sB1[f + 3]), 0.f);
    }
#pragma unroll
    for (int f = 0; f < H; f += 4) {
        unsigned long long acc01 = 0ull, acc23 = 0ull;
#pragma unroll
        for (int k = 0; k < H; k++) {
            const ulonglong2 w = *(const ulonglong2*)&sW2[k * H + f];
            unsigned long long zz = splat_f32x2(t[k]);
            fma_f32x2(acc01, zz, w.x);
            fma_f32x2(acc23, zz, w.y);
        }
        float a0, a1, a2, a3;
        unpack_f32x2(acc01, a0, a1);
        unpack_f32x2(acc23, a2, a3);
        float4 o;
        o.x = fmaxf(fmaf(a0, sA2[f + 0], sB2[f + 0]), 0.f);
        o.y = fmaxf(fmaf(a1, sA2[f + 1], sB2[f + 1]), 0.f);
        o.z = fmaxf(fmaf(a2, sA2[f + 2], sB2[f + 2]), 0.f);
        o.w = fmaxf(fmaf(a3, sA2[f + 3], sB2[f + 3]), 0.f);
        *(float4*)&g_h[(size_t)n * H + f] = o;
    }
}

// ---------------- PairNorm per graph segment: 256 threads, 4 rows in flight ----------------
__global__ void __launch_bounds__(256) k_pairnorm() {
    __shared__ float sS[4][H];
    __shared__ float sSS[4][H];
    __shared__ float sMean[H];
    __shared__ float sRed[H];
    __shared__ float sInv;
    int g = blockIdx.x;
    int sub = threadIdx.x >> 6, f = threadIdx.x & 63;
    int ns = g_gstart[g], ne = g_gstart[g + 1];
    float cnt = fmaxf((float)(ne - ns), 1.f);
    float s = 0.f, ss = 0.f;
    for (int n = ns + sub; n < ne; n += 4) {
        float v = g_h[(size_t)n * H + f];
        s += v;
        ss = fmaf(v, v, ss);
    }
    sS[sub][f] = s;
    sSS[sub][f] = ss;
    __syncthreads();
    if (sub == 0) {
        float st = sS[0][f] + sS[1][f] + sS[2][f] + sS[3][f];
        float sst = sSS[0][f] + sSS[1][f] + sSS[2][f] + sSS[3][f];
        float mean = st / cnt;
        sMean[f] = mean;
        sRed[f] = sst - cnt * mean * mean;
    }
    __syncthreads();
    if (threadIdx.x < 32) {
        float v = sRed[threadIdx.x] + sRed[threadIdx.x + 32];
#pragma unroll
        for (int o = 16; o > 0; o >>= 1) v += __shfl_down_sync(0xffffffffu, v, o);
        if (threadIdx.x == 0) sInv = 1.0f / sqrtf(PN_EPS + v / cnt);
    }
    __syncthreads();
    float inv = sInv, m = sMean[f];
    for (int n = ns + sub; n < ne; n += 4) {
        size_t idx = (size_t)n * H + f;
        g_h[idx] = (g_h[idx] - m) * inv;
    }
}

// ---------------- global_add_pool + classifier fused: 256 threads ----------------
__global__ void __launch_bounds__(256) k_pool_cls(const float* __restrict__ clsW,
                                                  const float* __restrict__ clsb,
                                                  float* __restrict__ out) {
    __shared__ float sS[4][H];
    __shared__ float r0[H], r1[H];
    int g = blockIdx.x;
    int sub = threadIdx.x >> 6, f = threadIdx.x & 63;
    int ns = g_gstart[g], ne = g_gstart[g + 1];
    float s = 0.f;
    for (int n = ns + sub; n < ne; n += 4) s += g_h[(size_t)n * H + f];
    sS[sub][f] = s;
    __syncthreads();
    if (sub == 0) {
        float st = sS[0][f] + sS[1][f] + sS[2][f] + sS[3][f];
        r0[f] = st * clsW[f * OUTF + 0];
        r1[f] = st * clsW[f * OUTF + 1];
    }
    __syncthreads();
    if (threadIdx.x < 32) {
        float v0 = r0[threadIdx.x] + r0[threadIdx.x + 32];
        float v1 = r1[threadIdx.x] + r1[threadIdx.x + 32];
#pragma unroll
        for (int o = 16; o > 0; o >>= 1) {
            v0 += __shfl_down_sync(0xffffffffu, v0, o);
            v1 += __shfl_down_sync(0xffffffffu, v1, o);
        }
        if (threadIdx.x == 0) {
            out[g * OUTF + 0] = v0 + clsb[0];
            out[g * OUTF + 1] = v1 + clsb[1];
        }
    }
}

// ---------------- launcher ----------------
extern "C" void kernel_launch(void* const* d_in, const int* in_sizes, int n_in,
                              void* d_out, int out_size) {
    const float* x        = (const float*)d_in[0];
    const int*   ei       = (const int*)d_in[1];
    const float* ea       = (const float*)d_in[2];
    const int*   batch    = (const int*)d_in[3];
    const float* lin_in_W = (const float*)d_in[4];
    const float* lin_in_b = (const float*)d_in[5];
    const float* edge_W   = (const float*)d_in[6];
    const float* edge_b   = (const float*)d_in[7];
    const float* mlp_W1   = (const float*)d_in[8];
    const float* mlp_b1   = (const float*)d_in[9];
    const float* mlp_bn_g = (const float*)d_in[10];
    const float* mlp_bn_b = (const float*)d_in[11];
    const float* mlp_bn_rm= (const float*)d_in[12];
    const float* mlp_bn_rv= (const float*)d_in[13];
    const float* mlp_W2   = (const float*)d_in[14];
    const float* mlp_b2   = (const float*)d_in[15];
    const float* eps      = (const float*)d_in[16];
    const float* bn_g     = (const float*)d_in[17];
    const float* bn_b     = (const float*)d_in[18];
    const float* bn_rm    = (const float*)d_in[19];
    const float* bn_rv    = (const float*)d_in[20];
    const float* cls_W    = (const float*)d_in[21];
    const float* cls_b    = (const float*)d_in[22];
    float* out = (float*)d_out;

    k_zero_lin<<<2 * LIN_BLOCKS, 128>>>(x, lin_in_W, lin_in_b);
    k_hist<<<(N_EDGES + 255) / 256, 256>>>(ei, batch);
    k_scans<<<2, 1024>>>();
    k_fill<<<(N_EDGES / 2 + 255) / 256, 256>>>(ei, ea);

    for (int i = 0; i < NLAYER; i++) {
        k_edge<<<(N_NODES * 32 + 255) / 256, 256>>>(edge_W + i * 4 * H, edge_b + i * H);
        k_node<<<(N_NODES + 127) / 128, 128>>>(
            mlp_W1 + i * H * H, mlp_b1 + i * H,
            mlp_bn_g + i * H, mlp_bn_b + i * H, mlp_bn_rm + i * H, mlp_bn_rv + i * H,
            mlp_W2 + i * H * H, mlp_b2 + i * H,
            bn_g + i * H, bn_b + i * H, bn_rm + i * H, bn_rv + i * H,
            eps + i);
        if (i < NLAYER - 1) k_pairnorm<<<GQ, 256>>>();
    }
    k_pool_cls<<<GQ, 256>>>(cls_W, cls_b, out);
}

// round 13
// speedup vs baseline: 1.1589x; 1.0196x over previous
#include <cuda_runtime.h>

#define N_NODES 50000
#define N_EDGES 800000
#define IN_F 32
#define H 64
#define GQ 512
#define OUTF 2
#define NLAYER 3
#define BN_EPS 1e-5f
#define PN_EPS 1e-5f
#define HIST_BLOCKS 3125   /* (N_EDGES+255)/256 */
#define LINB 196           /* (N_NODES+255)/256 */

// ---------------- scratch (static device globals; zero-initialized at load) ----------------
__device__ float g_h[N_NODES * H];
__device__ float g_agg[N_NODES * H];
__device__ int   g_deg[N_NODES];        // must be 0 at entry; re-zeroed by k_pool_cls
__device__ int   g_rowstart[N_NODES + 1];
__device__ int   g_cursor[N_NODES];
__device__ int   g_csr_src[N_EDGES];
__device__ float4 g_csr_attr[N_EDGES];
__device__ int   g_gcnt[GQ];            // must be 0 at entry; re-zeroed by k_pool_cls
__device__ int   g_gstart[GQ + 1];

// ---------------- packed f32x2 helpers ----------------
__device__ __forceinline__ unsigned long long splat_f32x2(float v) {
    unsigned long long r;
    unsigned int u = __float_as_uint(v);
    asm("mov.b64 %0, {%1, %1};" : "=l"(r) : "r"(u));
    return r;
}
__device__ __forceinline__ unsigned long long pack_f32x2(float lo, float hi) {
    unsigned long long r;
    asm("mov.b64 %0, {%1, %2};" : "=l"(r)
        : "r"(__float_as_uint(lo)), "r"(__float_as_uint(hi)));
    return r;
}
__device__ __forceinline__ void fma_f32x2(unsigned long long& acc,
                                          unsigned long long a,
                                          unsigned long long b) {
    asm("fma.rn.f32x2 %0, %1, %2, %0;" : "+l"(acc) : "l"(a), "l"(b));
}
__device__ __forceinline__ void unpack_f32x2(unsigned long long p, float& lo, float& hi) {
    unsigned int u0, u1;
    asm("mov.b64 {%0, %1}, %2;" : "=r"(u0), "=r"(u1) : "l"(p));
    lo = __uint_as_float(u0);
    hi = __uint_as_float(u1);
}

// ---------------- launch 1: histogram (blocks < HIST_BLOCKS) + h = x@Win + b ----------
__global__ void __launch_bounds__(256) k_hist_lin(const int* __restrict__ ei,
                                                  const int* __restrict__ batch,
                                                  const float* __restrict__ x,
                                                  const float* __restrict__ W,
                                                  const float* __restrict__ b) {
    __shared__ float sW[IN_F * H];
    __shared__ float sb[H];
    if (blockIdx.x < HIST_BLOCKS) {
        int i = blockIdx.x * 256 + threadIdx.x;
        if (i < N_EDGES) atomicAdd(&g_deg[ei[N_EDGES + i]], 1);
        if (i < N_NODES) atomicAdd(&g_gcnt[batch[i]], 1);
        return;
    }
    for (int i = threadIdx.x; i < IN_F * H; i += 256) sW[i] = W[i];
    if (threadIdx.x < H) sb[threadIdx.x] = b[threadIdx.x];
    __syncthreads();
    int n = (blockIdx.x - HIST_BLOCKS) * 256 + threadIdx.x;
    if (n >= N_NODES) return;
    float xr[IN_F];
    const float4* xp = (const float4*)(x + (size_t)n * IN_F);
#pragma unroll
    for (int k = 0; k < IN_F / 4; k++) {
        float4 v = xp[k];
        xr[4 * k + 0] = v.x; xr[4 * k + 1] = v.y; xr[4 * k + 2] = v.z; xr[4 * k + 3] = v.w;
    }
#pragma unroll
    for (int f = 0; f < H; f += 4) {
        float4 acc = make_float4(sb[f], sb[f + 1], sb[f + 2], sb[f + 3]);
#pragma unroll
        for (int k = 0; k < IN_F; k++) {
            float4 w = *(const float4*)&sW[k * H + f];
            acc.x = fmaf(xr[k], w.x, acc.x);
            acc.y = fmaf(xr[k], w.y, acc.y);
            acc.z = fmaf(xr[k], w.z, acc.z);
            acc.w = fmaf(xr[k], w.w, acc.w);
        }
        *(float4*)&g_h[(size_t)n * H + f] = acc;
    }
}

// ---------------- launch 2: both exclusive scans ----------------
__global__ void k_scans() {
    if (blockIdx.x == 0) {
        __shared__ int ssum[1024];
        const int t = threadIdx.x;
        const int C = (N_NODES + 1023) / 1024;  // 49
        int start = t * C;
        int end = min(start + C, N_NODES);
        int local = 0;
        for (int i = start; i < end; i++) local += g_deg[i];
        ssum[t] = local;
        __syncthreads();
        for (int off = 1; off < 1024; off <<= 1) {
            int v = 0;
            if (t >= off) v = ssum[t - off];
            __syncthreads();
            if (t >= off) ssum[t] += v;
            __syncthreads();
        }
        int prefix = (t == 0) ? 0 : ssum[t - 1];
        for (int i = start; i < end; i++) {
            g_rowstart[i] = prefix;
            g_cursor[i] = prefix;
            prefix += g_deg[i];
        }
        if (t == 1023) g_rowstart[N_NODES] = ssum[1023];
    } else {
        __shared__ int s[GQ];
        const int t = threadIdx.x;
        if (t < GQ) s[t] = g_gcnt[t];
        __syncthreads();
        for (int off = 1; off < GQ; off <<= 1) {
            int v = 0;
            if (t < GQ && t >= off) v = s[t - off];
            __syncthreads();
            if (t < GQ && t >= off) s[t] += v;
            __syncthreads();
        }
        if (t < GQ) g_gstart[t + 1] = s[t];
        if (t == 0) g_gstart[0] = 0;
    }
}

// ---------------- launch 3: fill CSR, 2 edges per thread ----------------
__global__ void k_fill(const int* __restrict__ ei, const float* __restrict__ ea) {
    int i = blockIdx.x * blockDim.x + threadIdx.x;
    int e0 = i * 2;
    if (e0 >= N_EDGES) return;
    int2 srcs = *(const int2*)(ei + e0);
    int2 dsts = *(const int2*)(ei + N_EDGES + e0);
    float4 a0 = __ldg((const float4*)ea + e0);
    float4 a1 = __ldg((const float4*)ea + e0 + 1);
    int p0 = atomicAdd(&g_cursor[dsts.x], 1);
    g_csr_src[p0] = srcs.x;
    g_csr_attr[p0] = a0;
    int p1 = atomicAdd(&g_cursor[dsts.y], 1);
    g_csr_src[p1] = srcs.y;
    g_csr_attr[p1] = a1;
}

// ---------------- per-layer edge aggregation (warp per dst, unroll-4, f32x2 FMA) -------
__global__ void k_edge(const float* __restrict__ eW, const float* __restrict__ eb) {
    int warp = (blockIdx.x * blockDim.x + threadIdx.x) >> 5;
    int lane = threadIdx.x & 31;
    if (warp >= N_NODES) return;
    int f0 = lane * 2;
    const unsigned long long W0 = pack_f32x2(eW[f0],       eW[f0 + 1]);
    const unsigned long long W1 = pack_f32x2(eW[64 + f0],  eW[64 + f0 + 1]);
    const unsigned long long W2 = pack_f32x2(eW[128 + f0], eW[128 + f0 + 1]);
    const unsigned long long W3 = pack_f32x2(eW[192 + f0], eW[192 + f0 + 1]);
    const unsigned long long Bb = pack_f32x2(eb[f0], eb[f0 + 1]);
    int js = g_rowstart[warp], je = g_rowstart[warp + 1];
    float a0 = 0.f, a1 = 0.f;
    int j = js;
    for (; j + 4 <= je; j += 4) {
        int s0 = __ldg(&g_csr_src[j + 0]);
        int s1 = __ldg(&g_csr_src[j + 1]);
        int s2 = __ldg(&g_csr_src[j + 2]);
        int s3 = __ldg(&g_csr_src[j + 3]);
        float4 t0 = __ldg(&g_csr_attr[j + 0]);
        float4 t1 = __ldg(&g_csr_attr[j + 1]);
        float4 t2 = __ldg(&g_csr_attr[j + 2]);
        float4 t3 = __ldg(&g_csr_attr[j + 3]);
        float2 h0 = *(const float2*)&g_h[(size_t)s0 * H + f0];
        float2 h1 = *(const float2*)&g_h[(size_t)s1 * H + f0];
        float2 h2 = *(const float2*)&g_h[(size_t)s2 * H + f0];
        float2 h3 = *(const float2*)&g_h[(size_t)s3 * H + f0];
        float e0, e1;
        unsigned long long p;
        p = Bb;
        fma_f32x2(p, splat_f32x2(t0.x), W0);
        fma_f32x2(p, splat_f32x2(t0.y), W1);
        fma_f32x2(p, splat_f32x2(t0.z), W2);
        fma_f32x2(p, splat_f32x2(t0.w), W3);
        unpack_f32x2(p, e0, e1);
        a0 += fmaxf(h0.x + e0, 0.f);
        a1 += fmaxf(h0.y + e1, 0.f);
        p = Bb;
        fma_f32x2(p, splat_f32x2(t1.x), W0);
        fma_f32x2(p, splat_f32x2(t1.y), W1);
        fma_f32x2(p, splat_f32x2(t1.z), W2);
        fma_f32x2(p, splat_f32x2(t1.w), W3);
        unpack_f32x2(p, e0, e1);
        a0 += fmaxf(h1.x + e0, 0.f);
        a1 += fmaxf(h1.y + e1, 0.f);
        p = Bb;
        fma_f32x2(p, splat_f32x2(t2.x), W0);
        fma_f32x2(p, splat_f32x2(t2.y), W1);
        fma_f32x2(p, splat_f32x2(t2.z), W2);
        fma_f32x2(p, splat_f32x2(t2.w), W3);
        unpack_f32x2(p, e0, e1);
        a0 += fmaxf(h2.x + e0, 0.f);
        a1 += fmaxf(h2.y + e1, 0.f);
        p = Bb;
        fma_f32x2(p, splat_f32x2(t3.x), W0);
        fma_f32x2(p, splat_f32x2(t3.y), W1);
        fma_f32x2(p, splat_f32x2(t3.z), W2);
        fma_f32x2(p, splat_f32x2(t3.w), W3);
        unpack_f32x2(p, e0, e1);
        a0 += fmaxf(h3.x + e0, 0.f);
        a1 += fmaxf(h3.y + e1, 0.f);
    }
    for (; j < je; j++) {
        int src = __ldg(&g_csr_src[j]);
        float4 at = __ldg(&g_csr_attr[j]);
        float2 hs = *(const float2*)&g_h[(size_t)src * H + f0];
        unsigned long long p = Bb;
        fma_f32x2(p, splat_f32x2(at.x), W0);
        fma_f32x2(p, splat_f32x2(at.y), W1);
        fma_f32x2(p, splat_f32x2(at.z), W2);
        fma_f32x2(p, splat_f32x2(at.w), W3);
        float e0, e1;
        unpack_f32x2(p, e0, e1);
        a0 += fmaxf(hs.x + e0, 0.f);
        a1 += fmaxf(hs.y + e1, 0.f);
    }
    *(float2*)&g_agg[(size_t)warp * H + f0] = make_float2(a0, a1);
}

// ---------------- per-layer node update with packed f32x2 FMA ----------------
__global__ void __launch_bounds__(128) k_node(
    const float* __restrict__ W1, const float* __restrict__ b1,
    const float* __restrict__ bn1g, const float* __restrict__ bn1b,
    const float* __restrict__ bn1rm, const float* __restrict__ bn1rv,
    const float* __restrict__ W2, const float* __restrict__ b2,
    const float* __restrict__ bn2g, const float* __restrict__ bn2b,
    const float* __restrict__ bn2rm, const float* __restrict__ bn2rv,
    const float* __restrict__ epsp) {
    __shared__ __align__(16) float sW1[H * H];
    __shared__ __align__(16) float sW2[H * H];
    __shared__ float sA1[H], sB1[H], sA2[H], sB2[H];
    for (int i = threadIdx.x; i < H * H; i += 128) { sW1[i] = W1[i]; sW2[i] = W2[i]; }
    if (threadIdx.x < H) {
        int f = threadIdx.x;
        float a1 = bn1g[f] * rsqrtf(bn1rv[f] + BN_EPS);
        sA1[f] = a1;
        sB1[f] = (b1[f] - bn1rm[f]) * a1 + bn1b[f];
        float a2 = bn2g[f] * rsqrtf(bn2rv[f] + BN_EPS);
        sA2[f] = a2;
        sB2[f] = (b2[f] - bn2rm[f]) * a2 + bn2b[f];
    }
    __syncthreads();
    int n = blockIdx.x * 128 + threadIdx.x;
    if (n >= N_NODES) return;
    float epsv = 1.0f + *epsp;
    float z[H];
#pragma unroll
    for (int k = 0; k < H; k += 4) {
        float4 hv = *(const float4*)&g_h[(size_t)n * H + k];
        float4 av = *(const float4*)&g_agg[(size_t)n * H + k];
        z[k + 0] = fmaf(epsv, hv.x, av.x);
        z[k + 1] = fmaf(epsv, hv.y, av.y);
        z[k + 2] = fmaf(epsv, hv.z, av.z);
        z[k + 3] = fmaf(epsv, hv.w, av.w);
    }
    float t[H];
#pragma unroll
    for (int f = 0; f < H; f += 4) {
        unsigned long long acc01 = 0ull, acc23 = 0ull;
#pragma unroll
        for (int k = 0; k < H; k++) {
            const ulonglong2 w = *(const ulonglong2*)&sW1[k * H + f];
            unsigned long long zz = splat_f32x2(z[k]);
            fma_f32x2(acc01, zz, w.x);
            fma_f32x2(acc23, zz, w.y);
        }
        float a0, a1, a2, a3;
        unpack_f32x2(acc01, a0, a1);
        unpack_f32x2(acc23, a2, a3);
        t[f + 0] = fmaxf(fmaf(a0, sA1[f + 0], sB1[f + 0]), 0.f);
        t[f + 1] = fmaxf(fmaf(a1, sA1[f + 1], sB1[f + 1]), 0.f);
        t[f + 2] = fmaxf(fmaf(a2, sA1[f + 2], sB1[f + 2]), 0.f);
        t[f + 3] = fmaxf(fmaf(a3, sA1[f + 3], sB1[f + 3]), 0.f);
    }
#pragma unroll
    for (int f = 0; f < H; f += 4) {
        unsigned long long acc01 = 0ull, acc23 = 0ull;
#pragma unroll
        for (int k = 0; k < H; k++) {
            const ulonglong2 w = *(const ulonglong2*)&sW2[k * H + f];
            unsigned long long zz = splat_f32x2(t[k]);
            fma_f32x2(acc01, zz, w.x);
            fma_f32x2(acc23, zz, w.y);
        }
        float a0, a1, a2, a3;
        unpack_f32x2(acc01, a0, a1);
        unpack_f32x2(acc23, a2, a3);
        float4 o;
        o.x = fmaxf(fmaf(a0, sA2[f + 0], sB2[f + 0]), 0.f);
        o.y = fmaxf(fmaf(a1, sA2[f + 1], sB2[f + 1]), 0.f);
        o.z = fmaxf(fmaf(a2, sA2[f + 2], sB2[f + 2]), 0.f);
        o.w = fmaxf(fmaf(a3, sA2[f + 3], sB2[f + 3]), 0.f);
        *(float4*)&g_h[(size_t)n * H + f] = o;
    }
}

// ---------------- PairNorm per graph segment: 256 threads, 4 rows in flight ----------------
__global__ void __launch_bounds__(256) k_pairnorm() {
    __shared__ float sS[4][H];
    __shared__ float sSS[4][H];
    __shared__ float sMean[H];
    __shared__ float sRed[H];
    __shared__ float sInv;
    int g = blockIdx.x;
    int sub = threadIdx.x >> 6, f = threadIdx.x & 63;
    int ns = g_gstart[g], ne = g_gstart[g + 1];
    float cnt = fmaxf((float)(ne - ns), 1.f);
    float s = 0.f, ss = 0.f;
    for (int n = ns + sub; n < ne; n += 4) {
        float v = g_h[(size_t)n * H + f];
        s += v;
        ss = fmaf(v, v, ss);
    }
    sS[sub][f] = s;
    sSS[sub][f] = ss;
    __syncthreads();
    if (sub == 0) {
        float st = sS[0][f] + sS[1][f] + sS[2][f] + sS[3][f];
        float sst = sSS[0][f] + sSS[1][f] + sSS[2][f] + sSS[3][f];
        float mean = st / cnt;
        sMean[f] = mean;
        sRed[f] = sst - cnt * mean * mean;
    }
    __syncthreads();
    if (threadIdx.x < 32) {
        float v = sRed[threadIdx.x] + sRed[threadIdx.x + 32];
#pragma unroll
        for (int o = 16; o > 0; o >>= 1) v += __shfl_down_sync(0xffffffffu, v, o);
        if (threadIdx.x == 0) sInv = 1.0f / sqrtf(PN_EPS + v / cnt);
    }
    __syncthreads();
    float inv = sInv, m = sMean[f];
    for (int n = ns + sub; n < ne; n += 4) {
        size_t idx = (size_t)n * H + f;
        g_h[idx] = (g_h[idx] - m) * inv;
    }
}

// ---------------- pool + classifier; tail blocks re-zero counters for next replay -------
__global__ void __launch_bounds__(256) k_pool_cls(const float* __restrict__ clsW,
                                                  const float* __restrict__ clsb,
                                                  float* __restrict__ out) {
    if (blockIdx.x >= GQ) {
        int i = (blockIdx.x - GQ) * 256 + threadIdx.x;
        if (i < N_NODES) g_deg[i] = 0;
        if (i < GQ) g_gcnt[i] = 0;
        return;
    }
    __shared__ float sS[4][H];
    __shared__ float r0[H], r1[H];
    int g = blockIdx.x;
    int sub = threadIdx.x >> 6, f = threadIdx.x & 63;
    int ns = g_gstart[g], ne = g_gstart[g + 1];
    float s = 0.f;
    for (int n = ns + sub; n < ne; n += 4) s += g_h[(size_t)n * H + f];
    sS[sub][f] = s;
    __syncthreads();
    if (sub == 0) {
        float st = sS[0][f] + sS[1][f] + sS[2][f] + sS[3][f];
        r0[f] = st * clsW[f * OUTF + 0];
        r1[f] = st * clsW[f * OUTF + 1];
    }
    __syncthreads();
    if (threadIdx.x < 32) {
        float v0 = r0[threadIdx.x] + r0[threadIdx.x + 32];
        float v1 = r1[threadIdx.x] + r1[threadIdx.x + 32];
#pragma unroll
        for (int o = 16; o > 0; o >>= 1) {
            v0 += __shfl_down_sync(0xffffffffu, v0, o);
            v1 += __shfl_down_sync(0xffffffffu, v1, o);
        }
        if (threadIdx.x == 0) {
            out[g * OUTF + 0] = v0 + clsb[0];
            out[g * OUTF + 1] = v1 + clsb[1];
        }
    }
}

// ---------------- launcher ----------------
extern "C" void kernel_launch(void* const* d_in, const int* in_sizes, int n_in,
                              void* d_out, int out_size) {
    const float* x        = (const float*)d_in[0];
    const int*   ei       = (const int*)d_in[1];
    const float* ea       = (const float*)d_in[2];
    const int*   batch    = (const int*)d_in[3];
    const float* lin_in_W = (const float*)d_in[4];
    const float* lin_in_b = (const float*)d_in[5];
    const float* edge_W   = (const float*)d_in[6];
    const float* edge_b   = (const float*)d_in[7];
    const float* mlp_W1   = (const float*)d_in[8];
    const float* mlp_b1   = (const float*)d_in[9];
    const float* mlp_bn_g = (const float*)d_in[10];
    const float* mlp_bn_b = (const float*)d_in[11];
    const float* mlp_bn_rm= (const float*)d_in[12];
    const float* mlp_bn_rv= (const float*)d_in[13];
    const float* mlp_W2   = (const float*)d_in[14];
    const float* mlp_b2   = (const float*)d_in[15];
    const float* eps      = (const float*)d_in[16];
    const float* bn_g     = (const float*)d_in[17];
    const float* bn_b     = (const float*)d_in[18];
    const float* bn_rm    = (const float*)d_in[19];
    const float* bn_rv    = (const float*)d_in[20];
    const float* cls_W    = (const float*)d_in[21];
    const float* cls_b    = (const float*)d_in[22];
    float* out = (float*)d_out;

    // counters (g_deg/g_gcnt) are zero on entry: zero-initialized at module load,
    // and re-zeroed at the end of every execution by k_pool_cls tail blocks.
    k_hist_lin<<<HIST_BLOCKS + LINB, 256>>>(ei, batch, x, lin_in_W, lin_in_b);
    k_scans<<<2, 1024>>>();
    k_fill<<<(N_EDGES / 2 + 255) / 256, 256>>>(ei, ea);

    for (int i = 0; i < NLAYER; i++) {
        k_edge<<<(N_NODES * 32 + 255) / 256, 256>>>(edge_W + i * 4 * H, edge_b + i * H);
        k_node<<<(N_NODES + 127) / 128, 128>>>(
            mlp_W1 + i * H * H, mlp_b1 + i * H,
            mlp_bn_g + i * H, mlp_bn_b + i * H, mlp_bn_rm + i * H, mlp_bn_rv + i * H,
            mlp_W2 + i * H * H, mlp_b2 + i * H,
            bn_g + i * H, bn_b + i * H, bn_rm + i * H, bn_rv + i * H,
            eps + i);
        if (i < NLAYER - 1) k_pairnorm<<<GQ, 256>>>();
    }
    k_pool_cls<<<GQ + LINB, 256>>>(cls_W, cls_b, out);
}

// round 14
// speedup vs baseline: 1.1659x; 1.0060x over previous
#include <cuda_runtime.h>

#define N_NODES 50000
#define N_EDGES 800000
#define IN_F 32
#define H 64
#define GQ 512
#define OUTF 2
#define NLAYER 3
#define BN_EPS 1e-5f
#define PN_EPS 1e-5f
#define HIST_BLOCKS 3125   /* (N_EDGES+255)/256 */
#define LINB 196           /* (N_NODES+255)/256 */

// ---------------- scratch (static device globals; zero-initialized at load) ----------------
__device__ float g_h[N_NODES * H];
__device__ float g_agg[N_NODES * H];
__device__ int   g_deg[N_NODES];        // must be 0 at entry; re-zeroed by k_pool_cls
__device__ int   g_rowstart[N_NODES + 1];
__device__ int   g_cursor[N_NODES];
__device__ int   g_csr_src[N_EDGES];
__device__ float4 g_csr_attr[N_EDGES];
__device__ int   g_gcnt[GQ];            // must be 0 at entry; re-zeroed by k_pool_cls
__device__ int   g_gstart[GQ + 1];

// ---------------- packed f32x2 helpers ----------------
__device__ __forceinline__ unsigned long long splat_f32x2(float v) {
    unsigned long long r;
    unsigned int u = __float_as_uint(v);
    asm("mov.b64 %0, {%1, %1};" : "=l"(r) : "r"(u));
    return r;
}
__device__ __forceinline__ unsigned long long pack_f32x2(float lo, float hi) {
    unsigned long long r;
    asm("mov.b64 %0, {%1, %2};" : "=l"(r)
        : "r"(__float_as_uint(lo)), "r"(__float_as_uint(hi)));
    return r;
}
__device__ __forceinline__ void fma_f32x2(unsigned long long& acc,
                                          unsigned long long a,
                                          unsigned long long b) {
    asm("fma.rn.f32x2 %0, %1, %2, %0;" : "+l"(acc) : "l"(a), "l"(b));
}
__device__ __forceinline__ void unpack_f32x2(unsigned long long p, float& lo, float& hi) {
    unsigned int u0, u1;
    asm("mov.b64 {%0, %1}, %2;" : "=r"(u0), "=r"(u1) : "l"(p));
    lo = __uint_as_float(u0);
    hi = __uint_as_float(u1);
}

// ---------------- launch 1: histogram (blocks < HIST_BLOCKS) + h = x@Win + b ----------
__global__ void __launch_bounds__(256) k_hist_lin(const int* __restrict__ ei,
                                                  const int* __restrict__ batch,
                                                  const float* __restrict__ x,
                                                  const float* __restrict__ W,
                                                  const float* __restrict__ b) {
    __shared__ float sW[IN_F * H];
    __shared__ float sb[H];
    if (blockIdx.x < HIST_BLOCKS) {
        int i = blockIdx.x * 256 + threadIdx.x;
        if (i < N_EDGES) atomicAdd(&g_deg[ei[N_EDGES + i]], 1);
        if (i < N_NODES) atomicAdd(&g_gcnt[batch[i]], 1);
        return;
    }
    for (int i = threadIdx.x; i < IN_F * H; i += 256) sW[i] = W[i];
    if (threadIdx.x < H) sb[threadIdx.x] = b[threadIdx.x];
    __syncthreads();
    int n = (blockIdx.x - HIST_BLOCKS) * 256 + threadIdx.x;
    if (n >= N_NODES) return;
    float xr[IN_F];
    const float4* xp = (const float4*)(x + (size_t)n * IN_F);
#pragma unroll
    for (int k = 0; k < IN_F / 4; k++) {
        float4 v = xp[k];
        xr[4 * k + 0] = v.x; xr[4 * k + 1] = v.y; xr[4 * k + 2] = v.z; xr[4 * k + 3] = v.w;
    }
#pragma unroll
    for (int f = 0; f < H; f += 4) {
        float4 acc = make_float4(sb[f], sb[f + 1], sb[f + 2], sb[f + 3]);
#pragma unroll
        for (int k = 0; k < IN_F; k++) {
            float4 w = *(const float4*)&sW[k * H + f];
            acc.x = fmaf(xr[k], w.x, acc.x);
            acc.y = fmaf(xr[k], w.y, acc.y);
            acc.z = fmaf(xr[k], w.z, acc.z);
            acc.w = fmaf(xr[k], w.w, acc.w);
        }
        *(float4*)&g_h[(size_t)n * H + f] = acc;
    }
}

// ---------------- launch 2: both exclusive scans ----------------
__global__ void k_scans() {
    if (blockIdx.x == 0) {
        __shared__ int ssum[1024];
        const int t = threadIdx.x;
        const int C = (N_NODES + 1023) / 1024;  // 49
        int start = t * C;
        int end = min(start + C, N_NODES);
        int local = 0;
        for (int i = start; i < end; i++) local += g_deg[i];
        ssum[t] = local;
        __syncthreads();
        for (int off = 1; off < 1024; off <<= 1) {
            int v = 0;
            if (t >= off) v = ssum[t - off];
            __syncthreads();
            if (t >= off) ssum[t] += v;
            __syncthreads();
        }
        int prefix = (t == 0) ? 0 : ssum[t - 1];
        for (int i = start; i < end; i++) {
            g_rowstart[i] = prefix;
            g_cursor[i] = prefix;
            prefix += g_deg[i];
        }
        if (t == 1023) g_rowstart[N_NODES] = ssum[1023];
    } else {
        __shared__ int s[GQ];
        const int t = threadIdx.x;
        if (t < GQ) s[t] = g_gcnt[t];
        __syncthreads();
        for (int off = 1; off < GQ; off <<= 1) {
            int v = 0;
            if (t < GQ && t >= off) v = s[t - off];
            __syncthreads();
            if (t < GQ && t >= off) s[t] += v;
            __syncthreads();
        }
        if (t < GQ) g_gstart[t + 1] = s[t];
        if (t == 0) g_gstart[0] = 0;
    }
}

// ---------------- launch 3: fill CSR, 2 edges per thread ----------------
__global__ void k_fill(const int* __restrict__ ei, const float* __restrict__ ea) {
    int i = blockIdx.x * blockDim.x + threadIdx.x;
    int e0 = i * 2;
    if (e0 >= N_EDGES) return;
    int2 srcs = *(const int2*)(ei + e0);
    int2 dsts = *(const int2*)(ei + N_EDGES + e0);
    float4 a0 = __ldg((const float4*)ea + e0);
    float4 a1 = __ldg((const float4*)ea + e0 + 1);
    int p0 = atomicAdd(&g_cursor[dsts.x], 1);
    g_csr_src[p0] = srcs.x;
    g_csr_attr[p0] = a0;
    int p1 = atomicAdd(&g_cursor[dsts.y], 1);
    g_csr_src[p1] = srcs.y;
    g_csr_attr[p1] = a1;
}

// ---------------- per-layer edge aggregation (warp per dst, unroll-4, dual acc) --------
__global__ void k_edge(const float* __restrict__ eW, const float* __restrict__ eb) {
    int warp = (blockIdx.x * blockDim.x + threadIdx.x) >> 5;
    int lane = threadIdx.x & 31;
    if (warp >= N_NODES) return;
    int f0 = lane * 2;
    const unsigned long long W0 = pack_f32x2(eW[f0],       eW[f0 + 1]);
    const unsigned long long W1 = pack_f32x2(eW[64 + f0],  eW[64 + f0 + 1]);
    const unsigned long long W2 = pack_f32x2(eW[128 + f0], eW[128 + f0 + 1]);
    const unsigned long long W3 = pack_f32x2(eW[192 + f0], eW[192 + f0 + 1]);
    const unsigned long long Bb = pack_f32x2(eb[f0], eb[f0 + 1]);
    int js = g_rowstart[warp], je = g_rowstart[warp + 1];
    float a0 = 0.f, a1 = 0.f;       // edges 0,2 of each group
    float c0 = 0.f, c1 = 0.f;       // edges 1,3 of each group (independent chain)
    int j = js;
    for (; j + 4 <= je; j += 4) {
        int s0 = __ldg(&g_csr_src[j + 0]);
        int s1 = __ldg(&g_csr_src[j + 1]);
        int s2 = __ldg(&g_csr_src[j + 2]);
        int s3 = __ldg(&g_csr_src[j + 3]);
        float4 t0 = __ldg(&g_csr_attr[j + 0]);
        float4 t1 = __ldg(&g_csr_attr[j + 1]);
        float4 t2 = __ldg(&g_csr_attr[j + 2]);
        float4 t3 = __ldg(&g_csr_attr[j + 3]);
        float2 h0 = *(const float2*)&g_h[(size_t)s0 * H + f0];
        float2 h1 = *(const float2*)&g_h[(size_t)s1 * H + f0];
        float2 h2 = *(const float2*)&g_h[(size_t)s2 * H + f0];
        float2 h3 = *(const float2*)&g_h[(size_t)s3 * H + f0];
        float e0, e1;
        unsigned long long p;
        p = Bb;
        fma_f32x2(p, splat_f32x2(t0.x), W0);
        fma_f32x2(p, splat_f32x2(t0.y), W1);
        fma_f32x2(p, splat_f32x2(t0.z), W2);
        fma_f32x2(p, splat_f32x2(t0.w), W3);
        unpack_f32x2(p, e0, e1);
        a0 += fmaxf(h0.x + e0, 0.f);
        a1 += fmaxf(h0.y + e1, 0.f);
        p = Bb;
        fma_f32x2(p, splat_f32x2(t1.x), W0);
        fma_f32x2(p, splat_f32x2(t1.y), W1);
        fma_f32x2(p, splat_f32x2(t1.z), W2);
        fma_f32x2(p, splat_f32x2(t1.w), W3);
        unpack_f32x2(p, e0, e1);
        c0 += fmaxf(h1.x + e0, 0.f);
        c1 += fmaxf(h1.y + e1, 0.f);
        p = Bb;
        fma_f32x2(p, splat_f32x2(t2.x), W0);
        fma_f32x2(p, splat_f32x2(t2.y), W1);
        fma_f32x2(p, splat_f32x2(t2.z), W2);
        fma_f32x2(p, splat_f32x2(t2.w), W3);
        unpack_f32x2(p, e0, e1);
        a0 += fmaxf(h2.x + e0, 0.f);
        a1 += fmaxf(h2.y + e1, 0.f);
        p = Bb;
        fma_f32x2(p, splat_f32x2(t3.x), W0);
        fma_f32x2(p, splat_f32x2(t3.y), W1);
        fma_f32x2(p, splat_f32x2(t3.z), W2);
        fma_f32x2(p, splat_f32x2(t3.w), W3);
        unpack_f32x2(p, e0, e1);
        c0 += fmaxf(h3.x + e0, 0.f);
        c1 += fmaxf(h3.y + e1, 0.f);
    }
    for (; j < je; j++) {
        int src = __ldg(&g_csr_src[j]);
        float4 at = __ldg(&g_csr_attr[j]);
        float2 hs = *(const float2*)&g_h[(size_t)src * H + f0];
        unsigned long long p = Bb;
        fma_f32x2(p, splat_f32x2(at.x), W0);
        fma_f32x2(p, splat_f32x2(at.y), W1);
        fma_f32x2(p, splat_f32x2(at.z), W2);
        fma_f32x2(p, splat_f32x2(at.w), W3);
        float e0, e1;
        unpack_f32x2(p, e0, e1);
        a0 += fmaxf(hs.x + e0, 0.f);
        a1 += fmaxf(hs.y + e1, 0.f);
    }
    *(float2*)&g_agg[(size_t)warp * H + f0] = make_float2(a0 + c0, a1 + c1);
}

// ---------------- per-layer node update: 16-wide f-blocks, 8 independent FFMA2 chains ---
__global__ void __launch_bounds__(128) k_node(
    const float* __restrict__ W1, const float* __restrict__ b1,
    const float* __restrict__ bn1g, const float* __restrict__ bn1b,
    const float* __restrict__ bn1rm, const float* __restrict__ bn1rv,
    const float* __restrict__ W2, const float* __restrict__ b2,
    const float* __restrict__ bn2g, const float* __restrict__ bn2b,
    const float* __restrict__ bn2rm, const float* __restrict__ bn2rv,
    const float* __restrict__ epsp) {
    __shared__ __align__(16) float sW1[H * H];
    __shared__ __align__(16) float sW2[H * H];
    __shared__ float sA1[H], sB1[H], sA2[H], sB2[H];
    for (int i = threadIdx.x; i < H * H; i += 128) { sW1[i] = W1[i]; sW2[i] = W2[i]; }
    if (threadIdx.x < H) {
        int f = threadIdx.x;
        float a1 = bn1g[f] * rsqrtf(bn1rv[f] + BN_EPS);
        sA1[f] = a1;
        sB1[f] = (b1[f] - bn1rm[f]) * a1 + bn1b[f];
        float a2 = bn2g[f] * rsqrtf(bn2rv[f] + BN_EPS);
        sA2[f] = a2;
        sB2[f] = (b2[f] - bn2rm[f]) * a2 + bn2b[f];
    }
    __syncthreads();
    int n = blockIdx.x * 128 + threadIdx.x;
    if (n >= N_NODES) return;
    float epsv = 1.0f + *epsp;
    float z[H];
#pragma unroll
    for (int k = 0; k < H; k += 4) {
        float4 hv = *(const float4*)&g_h[(size_t)n * H + k];
        float4 av = *(const float4*)&g_agg[(size_t)n * H + k];
        z[k + 0] = fmaf(epsv, hv.x, av.x);
        z[k + 1] = fmaf(epsv, hv.y, av.y);
        z[k + 2] = fmaf(epsv, hv.z, av.z);
        z[k + 3] = fmaf(epsv, hv.w, av.w);
    }
    float t[H];
#pragma unroll
    for (int fb = 0; fb < H; fb += 16) {
        unsigned long long acc[8];
#pragma unroll
        for (int i = 0; i < 8; i++) acc[i] = 0ull;
#pragma unroll
        for (int k = 0; k < H; k++) {
            const ulonglong2* wp = (const ulonglong2*)&sW1[k * H + fb];
            ulonglong2 wa = wp[0], wb = wp[1], wc = wp[2], wd = wp[3];
            unsigned long long zz = splat_f32x2(z[k]);
            fma_f32x2(acc[0], zz, wa.x);
            fma_f32x2(acc[1], zz, wa.y);
            fma_f32x2(acc[2], zz, wb.x);
            fma_f32x2(acc[3], zz, wb.y);
            fma_f32x2(acc[4], zz, wc.x);
            fma_f32x2(acc[5], zz, wc.y);
            fma_f32x2(acc[6], zz, wd.x);
            fma_f32x2(acc[7], zz, wd.y);
        }
#pragma unroll
        for (int i = 0; i < 8; i++) {
            float v0, v1;
            unpack_f32x2(acc[i], v0, v1);
            int f = fb + 2 * i;
            t[f + 0] = fmaxf(fmaf(v0, sA1[f + 0], sB1[f + 0]), 0.f);
            t[f + 1] = fmaxf(fmaf(v1, sA1[f + 1], sB1[f + 1]), 0.f);
        }
    }
#pragma unroll
    for (int fb = 0; fb < H; fb += 16) {
        unsigned long long acc[8];
#pragma unroll
        for (int i = 0; i < 8; i++) acc[i] = 0ull;
#pragma unroll
        for (int k = 0; k < H; k++) {
            const ulonglong2* wp = (const ulonglong2*)&sW2[k * H + fb];
            ulonglong2 wa = wp[0], wb = wp[1], wc = wp[2], wd = wp[3];
            unsigned long long zz = splat_f32x2(t[k]);
            fma_f32x2(acc[0], zz, wa.x);
            fma_f32x2(acc[1], zz, wa.y);
            fma_f32x2(acc[2], zz, wb.x);
            fma_f32x2(acc[3], zz, wb.y);
            fma_f32x2(acc[4], zz, wc.x);
            fma_f32x2(acc[5], zz, wc.y);
            fma_f32x2(acc[6], zz, wd.x);
            fma_f32x2(acc[7], zz, wd.y);
        }
#pragma unroll
        for (int i = 0; i < 8; i += 2) {
            float v0, v1, v2, v3;
            unpack_f32x2(acc[i], v0, v1);
            unpack_f32x2(acc[i + 1], v2, v3);
            int f = fb + 2 * i;
            float4 o;
            o.x = fmaxf(fmaf(v0, sA2[f + 0], sB2[f + 0]), 0.f);
            o.y = fmaxf(fmaf(v1, sA2[f + 1], sB2[f + 1]), 0.f);
            o.z = fmaxf(fmaf(v2, sA2[f + 2], sB2[f + 2]), 0.f);
            o.w = fmaxf(fmaf(v3, sA2[f + 3], sB2[f + 3]), 0.f);
            *(float4*)&g_h[(size_t)n * H + f] = o;
        }
    }
}

// ---------------- PairNorm per graph segment: 256 threads, 4 rows in flight ----------------
__global__ void __launch_bounds__(256) k_pairnorm() {
    __shared__ float sS[4][H];
    __shared__ float sSS[4][H];
    __shared__ float sMean[H];
    __shared__ float sRed[H];
    __shared__ float sInv;
    int g = blockIdx.x;
    int sub = threadIdx.x >> 6, f = threadIdx.x & 63;
    int ns = g_gstart[g], ne = g_gstart[g + 1];
    float cnt = fmaxf((float)(ne - ns), 1.f);
    float s = 0.f, ss = 0.f;
    for (int n = ns + sub; n < ne; n += 4) {
        float v = g_h[(size_t)n * H + f];
        s += v;
        ss = fmaf(v, v, ss);
    }
    sS[sub][f] = s;
    sSS[sub][f] = ss;
    __syncthreads();
    if (sub == 0) {
        float st = sS[0][f] + sS[1][f] + sS[2][f] + sS[3][f];
        float sst = sSS[0][f] + sSS[1][f] + sSS[2][f] + sSS[3][f];
        float mean = st / cnt;
        sMean[f] = mean;
        sRed[f] = sst - cnt * mean * mean;
    }
    __syncthreads();
    if (threadIdx.x < 32) {
        float v = sRed[threadIdx.x] + sRed[threadIdx.x + 32];
#pragma unroll
        for (int o = 16; o > 0; o >>= 1) v += __shfl_down_sync(0xffffffffu, v, o);
        if (threadIdx.x == 0) sInv = 1.0f / sqrtf(PN_EPS + v / cnt);
    }
    __syncthreads();
    float inv = sInv, m = sMean[f];
    for (int n = ns + sub; n < ne; n += 4) {
        size_t idx = (size_t)n * H + f;
        g_h[idx] = (g_h[idx] - m) * inv;
    }
}

// ---------------- pool + classifier; tail blocks re-zero counters for next replay -------
__global__ void __launch_bounds__(256) k_pool_cls(const float* __restrict__ clsW,
                                                  const float* __restrict__ clsb,
                                                  float* __restrict__ out) {
    if (blockIdx.x >= GQ) {
        int i = (blockIdx.x - GQ) * 256 + threadIdx.x;
        if (i < N_NODES) g_deg[i] = 0;
        if (i < GQ) g_gcnt[i] = 0;
        return;
    }
    __shared__ float sS[4][H];
    __shared__ float r0[H], r1[H];
    int g = blockIdx.x;
    int sub = threadIdx.x >> 6, f = threadIdx.x & 63;
    int ns = g_gstart[g], ne = g_gstart[g + 1];
    float s = 0.f;
    for (int n = ns + sub; n < ne; n += 4) s += g_h[(size_t)n * H + f];
    sS[sub][f] = s;
    __syncthreads();
    if (sub == 0) {
        float st = sS[0][f] + sS[1][f] + sS[2][f] + sS[3][f];
        r0[f] = st * clsW[f * OUTF + 0];
        r1[f] = st * clsW[f * OUTF + 1];
    }
    __syncthreads();
    if (threadIdx.x < 32) {
        float v0 = r0[threadIdx.x] + r0[threadIdx.x + 32];
        float v1 = r1[threadIdx.x] + r1[threadIdx.x + 32];
#pragma unroll
        for (int o = 16; o > 0; o >>= 1) {
            v0 += __shfl_down_sync(0xffffffffu, v0, o);
            v1 += __shfl_down_sync(0xffffffffu, v1, o);
        }
        if (threadIdx.x == 0) {
            out[g * OUTF + 0] = v0 + clsb[0];
            out[g * OUTF + 1] = v1 + clsb[1];
        }
    }
}

// ---------------- launcher ----------------
extern "C" void kernel_launch(void* const* d_in, const int* in_sizes, int n_in,
                              void* d_out, int out_size) {
    const float* x        = (const float*)d_in[0];
    const int*   ei       = (const int*)d_in[1];
    const float* ea       = (const float*)d_in[2];
    const int*   batch    = (const int*)d_in[3];
    const float* lin_in_W = (const float*)d_in[4];
    const float* lin_in_b = (const float*)d_in[5];
    const float* edge_W   = (const float*)d_in[6];
    const float* edge_b   = (const float*)d_in[7];
    const float* mlp_W1   = (const float*)d_in[8];
    const float* mlp_b1   = (const float*)d_in[9];
    const float* mlp_bn_g = (const float*)d_in[10];
    const float* mlp_bn_b = (const float*)d_in[11];
    const float* mlp_bn_rm= (const float*)d_in[12];
    const float* mlp_bn_rv= (const float*)d_in[13];
    const float* mlp_W2   = (const float*)d_in[14];
    const float* mlp_b2   = (const float*)d_in[15];
    const float* eps      = (const float*)d_in[16];
    const float* bn_g     = (const float*)d_in[17];
    const float* bn_b     = (const float*)d_in[18];
    const float* bn_rm    = (const float*)d_in[19];
    const float* bn_rv    = (const float*)d_in[20];
    const float* cls_W    = (const float*)d_in[21];
    const float* cls_b    = (const float*)d_in[22];
    float* out = (float*)d_out;

    // counters (g_deg/g_gcnt) are zero on entry: zero-initialized at module load,
    // and re-zeroed at the end of every execution by k_pool_cls tail blocks.
    k_hist_lin<<<HIST_BLOCKS + LINB, 256>>>(ei, batch, x, lin_in_W, lin_in_b);
    k_scans<<<2, 1024>>>();
    k_fill<<<(N_EDGES / 2 + 255) / 256, 256>>>(ei, ea);

    for (int i = 0; i < NLAYER; i++) {
        k_edge<<<(N_NODES * 32 + 255) / 256, 256>>>(edge_W + i * 4 * H, edge_b + i * H);
        k_node<<<(N_NODES + 127) / 128, 128>>>(
            mlp_W1 + i * H * H, mlp_b1 + i * H,
            mlp_bn_g + i * H, mlp_bn_b + i * H, mlp_bn_rm + i * H, mlp_bn_rv + i * H,
            mlp_W2 + i * H * H, mlp_b2 + i * H,
            bn_g + i * H, bn_b + i * H, bn_rm + i * H, bn_rv + i * H,
            eps + i);
        if (i < NLAYER - 1) k_pairnorm<<<GQ, 256>>>();
    }
    k_pool_cls<<<GQ + LINB, 256>>>(cls_W, cls_b, out);
}